// round 16
// baseline (speedup 1.0000x reference)
#include <cuda_runtime.h>
#include <cuda_fp16.h>
#include <math.h>
#include <stdint.h>

#define BSZ 64
#define TT  512
#define DD  768
#define WW  255
#define HH  8
#define DHD 96
#define BW  (BSZ*WW)      // 16320
#define DFF 3072
#define NQKV 2304

// ---------------- scratch (device globals; no allocation allowed) ----------
static __device__ float  g_feat[BW*DD];
static __device__ float  g_qkv[(long)BW*NQKV];
static __device__ float  g_tmp[BW*DD];
static __device__ float  g_tmp2[BW*DD];
static __device__ float  g_x[BW*DD];
static __device__ __half g_aexpA[(long)BW*2*DD];     // [M, 1536] halfs
static __device__ __half g_aexpB[(long)BW*2*DFF];    // [M, 6144] halfs
static __device__ __half g_wqkv[NQKV*2*DD];          // [2304][1536]
static __device__ __half g_wo[DD*2*DD];
static __device__ __half g_w1[DFF*2*DD];             // [3072][1536]
static __device__ __half g_w2[DD*2*DFF];             // [768][6144]
static __device__ float  g_bqkv[NQKV];

// ---------------- helpers ----------------------------------------------------
#define CP16(d,s)  asm volatile("cp.async.cg.shared.global [%0], [%1], 16;" :: "r"(d), "l"(s))
#define CPCOMMIT() asm volatile("cp.async.commit_group;" ::: "memory")
#define CPWAIT1()  asm volatile("cp.async.wait_group 1;" ::: "memory")

#define LDSM4(r0,r1,r2,r3,addr) \
    asm volatile("ldmatrix.sync.aligned.m8n8.x4.shared.b16 {%0,%1,%2,%3}, [%4];" \
        : "=r"(r0), "=r"(r1), "=r"(r2), "=r"(r3) : "r"(addr))

__device__ __forceinline__ uint32_t smem_u32(const void* p){
    uint32_t a;
    asm("{ .reg .u64 t; cvta.to.shared.u64 t, %1; cvt.u32.u64 %0, t; }" : "=r"(a) : "l"(p));
    return a;
}

__device__ __forceinline__ void mma_f16(float* c, const uint32_t* a, const uint32_t* b){
    asm volatile(
        "mma.sync.aligned.m16n8k16.row.col.f32.f16.f16.f32 "
        "{%0,%1,%2,%3}, {%4,%5,%6,%7}, {%8,%9}, {%0,%1,%2,%3};"
        : "+f"(c[0]), "+f"(c[1]), "+f"(c[2]), "+f"(c[3])
        : "r"(a[0]), "r"(a[1]), "r"(a[2]), "r"(a[3]), "r"(b[0]), "r"(b[1]));
}

__device__ __forceinline__ void split2(float v, __half& h, __half& l){
    h = __float2half_rn(v);
    l = __float2half_rn(v - __half2float(h));
}

// ---- packed f32x2 (Blackwell FFMA2) ----
__device__ __forceinline__ unsigned long long pk2(float x, float y){
    unsigned long long r;
    asm("mov.b64 %0, {%1, %2};" : "=l"(r) : "f"(x), "f"(y));
    return r;
}
__device__ __forceinline__ void fma2(unsigned long long& acc, unsigned long long a,
                                     unsigned long long b){
    asm("fma.rn.f32x2 %0, %1, %2, %0;" : "+l"(acc) : "l"(a), "l"(b));
}
__device__ __forceinline__ float2 upk2(unsigned long long v){
    float x, y;
    asm("mov.b64 {%0, %1}, %2;" : "=f"(x), "=f"(y) : "l"(v));
    return make_float2(x, y);
}

// ---------------- fused weight prep: transpose + fp16 hi/lo split -----------
__global__ void prep_weights_k(
    const float* __restrict__ Wq, const float* __restrict__ Wk,
    const float* __restrict__ Wv, const float* __restrict__ Wo,
    const float* __restrict__ W1, const float* __restrict__ W2,
    __half* wqkv, __half* wo, __half* w1, __half* w2)
{
    __shared__ float t[32][33];
    int z = blockIdx.z;
    const float* W; __half* Bx; int K, N;
    switch (z) {
        case 0: W = Wq; Bx = wqkv;                 K = DD;  N = DD;  break;
        case 1: W = Wk; Bx = wqkv + 768L*2*DD;     K = DD;  N = DD;  break;
        case 2: W = Wv; Bx = wqkv + 1536L*2*DD;    K = DD;  N = DD;  break;
        case 3: W = Wo; Bx = wo;                   K = DD;  N = DD;  break;
        case 4: W = W1; Bx = w1;                   K = DD;  N = DFF; break;
        default:W = W2; Bx = w2;                   K = DFF; N = DD;  break;
    }
    int n0 = blockIdx.x * 32, k0 = blockIdx.y * 32;
    if (n0 >= N || k0 >= K) return;
    int tx = threadIdx.x & 31, ty = threadIdx.x >> 5;
    #pragma unroll
    for (int r = ty; r < 32; r += 8)
        t[r][tx] = W[(long)(k0 + r) * N + n0 + tx];
    __syncthreads();
    #pragma unroll
    for (int r = ty; r < 32; r += 8) {
        float v = t[tx][r];
        __half h, l; split2(v, h, l);
        long b = (long)(n0 + r) * (2 * K) + k0 + tx;
        Bx[b] = h;
        Bx[b + K] = l;
    }
}

__global__ void concat_bias_k(const float* __restrict__ bq, const float* __restrict__ bk,
                              const float* __restrict__ bv, float* __restrict__ bqkv) {
    int i = blockIdx.x * 256 + threadIdx.x;
    if (i < DD) {
        bqkv[i] = bq[i];
        bqkv[DD + i] = bk[i];
        bqkv[2*DD + i] = bv[i];
    }
}

// ---------------- fused gather: first-subtoken + copy + split ---------------
__global__ __launch_bounds__(256)
void gather_fused_k(const float* __restrict__ ob, const int* __restrict__ wi,
                    float* __restrict__ feat, __half* __restrict__ aexpA) {
    __shared__ int first[WW];
    int b = blockIdx.x, tid = threadIdx.x;
    for (int i = tid; i < WW; i += 256) first[i] = TT;
    __syncthreads();
    for (int t = tid; t < TT; t += 256) {
        int w = wi[b * TT + t];
        if (w >= 0 && w < WW) atomicMin(&first[w], t);
    }
    __syncthreads();
    for (int idx = tid; idx < WW * 192; idx += 256) {
        int row = idx / 192, c4 = idx % 192;
        int t = first[row]; if (t >= TT) t = 0;
        float4 val = ((const float4*)(ob + ((long)(b * TT + t)) * DD))[c4];
        long gr = (long)b * WW + row;
        ((float4*)(feat + gr * DD))[c4] = val;
        float vv[4] = {val.x, val.y, val.z, val.w};
        __half hs[4], ls[4];
        #pragma unroll
        for (int j = 0; j < 4; j++) split2(vv[j], hs[j], ls[j]);
        __half2* ph = (__half2*)(aexpA + gr * 1536 + c4 * 4);
        ph[0] = __halves2half2(hs[0], hs[1]);
        ph[1] = __halves2half2(hs[2], hs[3]);
        __half2* pl = (__half2*)(aexpA + gr * 1536 + 768 + c4 * 4);
        pl[0] = __halves2half2(ls[0], ls[1]);
        pl[1] = __halves2half2(ls[2], ls[3]);
    }
}

// ---------------- fp16x3 GEMM, 512 thr, 128x128xKT64, 3-stage ---------------
#define KT 64
#define SH 72
#define A_HALFS (128*SH)                 // 9216
#define B_HALFS (128*SH)                 // 9216
#define NSTG 3
#define STG_HALFS (2*A_HALFS + 2*B_HALFS)  // 36864
#define STG_BYTES (STG_HALFS*2)          // 73728
#define GEMM_SMEM (NSTG*STG_BYTES)       // 221184

__global__ __launch_bounds__(512)
void gemm_f16_k(const __half* __restrict__ A2, const __half* __restrict__ B2,
                const float* __restrict__ bias, float* __restrict__ C0,
                float* __restrict__ C1, __half* __restrict__ Csplit,
                int M, int N, int Kfull, int Keff, int relu)
{
    extern __shared__ __half smh[];
    uint32_t sb = smem_u32(smh);
    int tid = threadIdx.x, wid = tid >> 5, lane = tid & 31;
    int g = lane >> 2, tg = lane & 3;
    int wm = wid & 3, wn = wid >> 2;            // 4 x 4 warps, warp tile 32x32
    int z = blockIdx.z;
    int kbase = z * Keff;
    float* C = z ? C1 : C0;
    const float* bp = z ? nullptr : bias;
    const int K2 = 2 * Kfull;
    const int S = Keff / KT;
    const long mrow0 = (long)blockIdx.y * 128;
    const long nrow0 = (long)blockIdx.x * 128;

    uint32_t aOff[2], bOff[2];
    {
        int r = wm * 32 + (lane & 15);
        int kc = (lane >> 4) * 8;
        #pragma unroll
        for (int mf = 0; mf < 2; mf++)
            aOff[mf] = (uint32_t)((r + mf * 16) * (SH * 2) + kc * 2);
        int q = lane >> 3, rl = lane & 7;
        int nn = wn * 32 + ((q >> 1) * 8) + rl;
        int kk = (q & 1) * 8;
        #pragma unroll
        for (int p = 0; p < 2; p++)
            bOff[p] = (uint32_t)((nn + p * 16) * (SH * 2) + kk * 2);
    }

    float acc[2][4][4];
    #pragma unroll
    for (int i = 0; i < 2; i++)
        #pragma unroll
        for (int j = 0; j < 4; j++)
            #pragma unroll
            for (int r = 0; r < 4; r++) acc[i][j][r] = 0.f;

    // per stage: A 128 rows x 8 chunks (paired hi/lo), B same -> 2+2 iters
    #define LOAD_STAGE(ks, slot) do { \
        uint32_t base_ = sb + (slot) * STG_BYTES; \
        _Pragma("unroll") \
        for (int i_ = 0; i_ < 2; i_++) { \
            int idx_ = i_ * 512 + tid; int r_ = idx_ >> 3, q_ = idx_ & 7; \
            long grow_ = mrow0 + r_; if (grow_ >= M) grow_ = M - 1; \
            const __half* s_ = A2 + grow_ * K2 + kbase + (ks) * KT + q_ * 8; \
            uint32_t d_ = base_ + (uint32_t)(r_ * (SH*2) + q_ * 16); \
            CP16(d_, s_); \
            CP16(d_ + A_HALFS*2, s_ + Kfull); \
        } \
        _Pragma("unroll") \
        for (int i_ = 0; i_ < 2; i_++) { \
            int idx_ = i_ * 512 + tid; int r_ = idx_ >> 3, q_ = idx_ & 7; \
            const __half* s_ = B2 + (long)(nrow0 + r_) * K2 + kbase + (ks) * KT + q_ * 8; \
            uint32_t d_ = base_ + (uint32_t)(2*A_HALFS*2 + r_ * (SH*2) + q_ * 16); \
            CP16(d_, s_); \
            CP16(d_ + B_HALFS*2, s_ + Kfull); \
        } \
    } while (0)

    LOAD_STAGE(0, 0); CPCOMMIT();
    LOAD_STAGE(1, 1); CPCOMMIT();

    for (int it = 0; it < S; it++) {
        int slot = it % NSTG;
        CPWAIT1();           // groups <= it complete -> stage it ready
        __syncthreads();     // all warps done with compute(it-1) -> slot (it+2)%3 free
        int lt = it + 2;
        if (lt < S) { LOAD_STAGE(lt, lt % NSTG); }
        CPCOMMIT();          // always commit (possibly empty) to keep numbering

        uint32_t stAh = sb + slot * STG_BYTES;
        uint32_t stAl = stAh + A_HALFS * 2;
        uint32_t stBh = stAh + 2 * A_HALFS * 2;
        uint32_t stBl = stBh + B_HALFS * 2;

        #pragma unroll
        for (int ks = 0; ks < 4; ks++) {
            uint32_t kb = (uint32_t)(ks * 32);
            uint32_t ah[2][4], al[2][4], bh[2][4], bl[2][4];
            #pragma unroll
            for (int mf = 0; mf < 2; mf++)
                LDSM4(ah[mf][0], ah[mf][1], ah[mf][2], ah[mf][3], stAh + aOff[mf] + kb);
            #pragma unroll
            for (int mf = 0; mf < 2; mf++)
                LDSM4(al[mf][0], al[mf][1], al[mf][2], al[mf][3], stAl + aOff[mf] + kb);
            #pragma unroll
            for (int p = 0; p < 2; p++)
                LDSM4(bh[p][0], bh[p][1], bh[p][2], bh[p][3], stBh + bOff[p] + kb);
            #pragma unroll
            for (int p = 0; p < 2; p++)
                LDSM4(bl[p][0], bl[p][1], bl[p][2], bl[p][3], stBl + bOff[p] + kb);

            #pragma unroll
            for (int mf = 0; mf < 2; mf++)
                #pragma unroll
                for (int p = 0; p < 2; p++) {
                    mma_f16(acc[mf][2*p],   ah[mf], &bh[p][0]);
                    mma_f16(acc[mf][2*p+1], ah[mf], &bh[p][2]);
                }
            #pragma unroll
            for (int mf = 0; mf < 2; mf++)
                #pragma unroll
                for (int p = 0; p < 2; p++) {
                    mma_f16(acc[mf][2*p],   ah[mf], &bl[p][0]);
                    mma_f16(acc[mf][2*p+1], ah[mf], &bl[p][2]);
                }
            #pragma unroll
            for (int mf = 0; mf < 2; mf++)
                #pragma unroll
                for (int p = 0; p < 2; p++) {
                    mma_f16(acc[mf][2*p],   al[mf], &bh[p][0]);
                    mma_f16(acc[mf][2*p+1], al[mf], &bh[p][2]);
                }
        }
    }

    // epilogue
    #pragma unroll
    for (int mf = 0; mf < 2; mf++) {
        long r0 = mrow0 + wm * 32 + mf * 16 + g;
        long r1 = r0 + 8;
        #pragma unroll
        for (int nf = 0; nf < 4; nf++) {
            long col = nrow0 + wn * 32 + nf * 8 + 2 * tg;
            float b0 = bp ? bp[col] : 0.f, b1 = bp ? bp[col + 1] : 0.f;
            float v0 = acc[mf][nf][0] + b0, v1 = acc[mf][nf][1] + b1;
            float v2 = acc[mf][nf][2] + b0, v3 = acc[mf][nf][3] + b1;
            if (relu) {
                v0 = fmaxf(v0, 0.f); v1 = fmaxf(v1, 0.f);
                v2 = fmaxf(v2, 0.f); v3 = fmaxf(v3, 0.f);
            }
            if (Csplit) {
                __half h0, l0, h1, l1;
                if (r0 < M) {
                    split2(v0, h0, l0); split2(v1, h1, l1);
                    *(__half2*)&Csplit[r0 * (2*(long)N) + col]     = __halves2half2(h0, h1);
                    *(__half2*)&Csplit[r0 * (2*(long)N) + N + col] = __halves2half2(l0, l1);
                }
                if (r1 < M) {
                    split2(v2, h0, l0); split2(v3, h1, l1);
                    *(__half2*)&Csplit[r1 * (2*(long)N) + col]     = __halves2half2(h0, h1);
                    *(__half2*)&Csplit[r1 * (2*(long)N) + N + col] = __halves2half2(l0, l1);
                }
            } else {
                if (r0 < M) *(float2*)&C[r0 * N + col] = make_float2(v0, v1);
                if (r1 < M) *(float2*)&C[r1 * N + col] = make_float2(v2, v3);
            }
        }
    }
}

// ---------------- attention: 512 thr, pair-interleaved K, packed f32x2 ------
#define AT_KS   (96*WW)          // 24480 floats (even)
#define AT_VS   (WW*97 + 1)      // 24736 floats (even -> ps 8B-aligned)
#define AT_PS   (32*256)
#define ATTN_SMEM ((AT_KS + AT_VS + AT_PS) * 4)   // 229,632 B

__global__ __launch_bounds__(512)
void attn2_k(const float* __restrict__ qkv, __half* __restrict__ ctx_split) {
    int b = blockIdx.x / HH, h = blockIdx.x % HH;
    extern __shared__ float smfa[];
    float* ks_t = smfa;                // pair-interleaved [48][255][2]
    float* vs   = ks_t + AT_KS;
    float* ps   = vs + AT_VS;          // even float offset -> 8B aligned
    float* qs   = ps;
    int tid = threadIdx.x, warp = tid >> 5, lane = tid & 31;

    for (int idx = tid; idx < WW * DHD; idx += 512) {
        int key = idx / DHD, d = idx % DHD;
        long gg = ((long)(b * WW + key)) * NQKV + h * DHD + d;
        ks_t[(d >> 1) * (2 * WW) + key * 2 + (d & 1)] = qkv[gg + DD];
        vs[key * 97 + d] = qkv[gg + 2 * DD];
    }
    __syncthreads();

    const float scale = 0.10206207261596575f;
    int d0 = lane * 3;

    for (int row0 = 0; row0 < 256; row0 += 32) {
        for (int idx = tid; idx < 32 * DHD; idx += 512) {
            int r = idx / DHD, d = idx % DHD;
            int row = row0 + r;
            qs[r * DHD + d] = (row < WW)
                ? qkv[((long)(b * WW + row)) * NQKV + h * DHD + d] : 0.f;
        }
        __syncthreads();

        unsigned long long acc2[8][2];
        #pragma unroll
        for (int kk = 0; kk < 8; kk++) {
            acc2[kk][0] = 0ull; acc2[kk][1] = 0ull;
        }

        const float* qr = &qs[(warp * 2) * DHD];
        #pragma unroll 4
        for (int dp = 0; dp < 48; dp++) {
            float2 t0 = *(const float2*)&qr[2 * dp];
            float2 t1 = *(const float2*)&qr[DHD + 2 * dp];
            unsigned long long qp0 = pk2(t0.x, t0.y);
            unsigned long long qp1 = pk2(t1.x, t1.y);
            const float2* kd = (const float2*)&ks_t[dp * (2 * WW)];
            #pragma unroll
            for (int kk = 0; kk < 8; kk++) {
                int key = lane + kk * 32;
                float2 kv2 = kd[key];
                unsigned long long kvp = pk2(kv2.x, kv2.y);
                fma2(acc2[kk][0], kvp, qp0);
                fma2(acc2[kk][1], kvp, qp1);
            }
        }
        float sc[8][2];
        #pragma unroll
        for (int kk = 0; kk < 8; kk++)
            #pragma unroll
            for (int r = 0; r < 2; r++) {
                float2 t = upk2(acc2[kk][r]);
                sc[kk][r] = t.x + t.y;
            }
        __syncthreads();

        float inv[2], mx[2];
        #pragma unroll
        for (int r = 0; r < 2; r++) {
            float m = -1e30f;
            #pragma unroll
            for (int kk = 0; kk < 8; kk++) {
                int key = lane + kk * 32;
                float s = (key < WW) ? sc[kk][r] * scale : -1e30f;
                sc[kk][r] = s;
                m = fmaxf(m, s);
            }
            #pragma unroll
            for (int o = 16; o; o >>= 1) m = fmaxf(m, __shfl_xor_sync(0xffffffffu, m, o));
            mx[r] = m;
        }
        #pragma unroll
        for (int r = 0; r < 2; r++) {
            float sum = 0.f;
            #pragma unroll
            for (int kk = 0; kk < 8; kk++) {
                float e = (sc[kk][r] > -1e29f) ? __expf(sc[kk][r] - mx[r]) : 0.f;
                sc[kk][r] = e;
                sum += e;
            }
            #pragma unroll
            for (int o = 16; o; o >>= 1) sum += __shfl_xor_sync(0xffffffffu, sum, o);
            inv[r] = 1.f / sum;
        }
        #pragma unroll
        for (int r = 0; r < 2; r++)
            #pragma unroll
            for (int kk = 0; kk < 8; kk++)
                ps[(warp * 2 + r) * 256 + lane + kk * 32] = sc[kk][r] * inv[r];
        __syncwarp();

        unsigned long long ap[2][3];
        #pragma unroll
        for (int r = 0; r < 2; r++)
            #pragma unroll
            for (int j = 0; j < 3; j++) ap[r][j] = 0ull;

        const float* pr = &ps[(warp * 2) * 256];
        #pragma unroll 2
        for (int key = 0; key < WW - 1; key += 2) {
            const float* vr0 = &vs[key * 97 + d0];
            const float* vr1 = vr0 + 97;
            unsigned long long vvp0 = pk2(vr0[0], vr1[0]);
            unsigned long long vvp1 = pk2(vr0[1], vr1[1]);
            unsigned long long vvp2 = pk2(vr0[2], vr1[2]);
            #pragma unroll
            for (int r = 0; r < 2; r++) {
                float2 pp = *(const float2*)&pr[r * 256 + key];
                unsigned long long ppk = pk2(pp.x, pp.y);
                fma2(ap[r][0], ppk, vvp0);
                fma2(ap[r][1], ppk, vvp1);
                fma2(ap[r][2], ppk, vvp2);
            }
        }
        const float* vrt = &vs[(WW - 1) * 97 + d0];
        #pragma unroll
        for (int r = 0; r < 2; r++) {
            int row = row0 + warp * 2 + r;
            if (row < WW) {
                float pt = pr[r * 256 + (WW - 1)];
                long base = ((long)(b * WW + row)) * 1536 + h * DHD + d0;
                #pragma unroll
                for (int j = 0; j < 3; j++) {
                    float2 t = upk2(ap[r][j]);
                    float val = t.x + t.y + pt * vrt[j];
                    __half hh, ll; split2(val, hh, ll);
                    ctx_split[base + j] = hh;
                    ctx_split[base + 768 + j] = ll;
                }
            }
        }
        __syncthreads();
    }
}

// ---------------- block reduce helper ---------------------------------------
__device__ __forceinline__ float block_reduce_sum(float val, float* red) {
    int lane = threadIdx.x & 31, warp = threadIdx.x >> 5;
    #pragma unroll
    for (int o = 16; o; o >>= 1) val += __shfl_xor_sync(0xffffffffu, val, o);
    if (lane == 0) red[warp] = val;
    __syncthreads();
    if (warp == 0) {
        float v = (lane < 8) ? red[lane] : 0.f;
        #pragma unroll
        for (int o = 4; o; o >>= 1) v += __shfl_xor_sync(0xffffffffu, v, o);
        if (lane == 0) red[0] = v;
    }
    __syncthreads();
    float r = red[0];
    __syncthreads();
    return r;
}

// ---------------- residual add (2 partials) + layernorm + split out ---------
__global__ __launch_bounds__(256)
void add_ln_k(const float* __restrict__ X, const float* __restrict__ Y1,
              const float* __restrict__ Y2,
              const float* __restrict__ g, const float* __restrict__ bb,
              float* __restrict__ out, __half* __restrict__ split) {
    __shared__ float red[32];
    int row = blockIdx.x, tid = threadIdx.x;
    const float* x = X + (long)row * DD;
    const float* y1 = Y1 + (long)row * DD;
    const float* y2 = Y2 + (long)row * DD;
    float v[3];
    float s = 0.f;
    #pragma unroll
    for (int i = 0; i < 3; i++) {
        int c = tid + 256 * i;
        v[i] = x[c] + y1[c] + y2[c];
        s += v[i];
    }
    float mean = block_reduce_sum(s, red) * (1.f / DD);
    float vs = 0.f;
    #pragma unroll
    for (int i = 0; i < 3; i++) { float d = v[i] - mean; vs += d * d; }
    float var = block_reduce_sum(vs, red) * (1.f / DD);
    float rstd = rsqrtf(var + 1e-5f);
    float* o = out + (long)row * DD;
    #pragma unroll
    for (int i = 0; i < 3; i++) {
        int c = tid + 256 * i;
        float val = (v[i] - mean) * rstd * g[c] + bb[c];
        o[c] = val;
        if (split) {
            __half h, l; split2(val, h, l);
            split[(long)row * 1536 + c] = h;
            split[(long)row * 1536 + 768 + c] = l;
        }
    }
}

// ---------------- final: add + LN2 + LN3 + linear(2) + softmax + argmax -----
__global__ __launch_bounds__(256)
void final2_k(const float* __restrict__ X, const float* __restrict__ Y1,
              const float* __restrict__ Y2,
              const float* __restrict__ g2, const float* __restrict__ b2,
              const float* __restrict__ g3, const float* __restrict__ b3,
              const float* __restrict__ lw, const float* __restrict__ lb,
              float* __restrict__ probs, float* __restrict__ path, int write_path) {
    __shared__ float red[32];
    int row = blockIdx.x, tid = threadIdx.x;
    const float* x = X + (long)row * DD;
    const float* y1 = Y1 + (long)row * DD;
    const float* y2 = Y2 + (long)row * DD;
    float v[3];
    float s = 0.f;
    #pragma unroll
    for (int i = 0; i < 3; i++) {
        int c = tid + 256 * i;
        v[i] = x[c] + y1[c] + y2[c];
        s += v[i];
    }
    float mean = block_reduce_sum(s, red) * (1.f / DD);
    float vs = 0.f;
    #pragma unroll
    for (int i = 0; i < 3; i++) { float d = v[i] - mean; vs += d * d; }
    float var = block_reduce_sum(vs, red) * (1.f / DD);
    float rstd = rsqrtf(var + 1e-5f);
    #pragma unroll
    for (int i = 0; i < 3; i++) {
        int c = tid + 256 * i;
        v[i] = (v[i] - mean) * rstd * g2[c] + b2[c];
    }
    s = 0.f;
    #pragma unroll
    for (int i = 0; i < 3; i++) s += v[i];
    mean = block_reduce_sum(s, red) * (1.f / DD);
    vs = 0.f;
    #pragma unroll
    for (int i = 0; i < 3; i++) { float d = v[i] - mean; vs += d * d; }
    var = block_reduce_sum(vs, red) * (1.f / DD);
    rstd = rsqrtf(var + 1e-5f);
    float l0 = 0.f, l1 = 0.f;
    #pragma unroll
    for (int i = 0; i < 3; i++) {
        int c = tid + 256 * i;
        float yv = (v[i] - mean) * rstd * g3[c] + b3[c];
        l0 += yv * lw[2 * c + 0];
        l1 += yv * lw[2 * c + 1];
    }
    l0 = block_reduce_sum(l0, red);
    l1 = block_reduce_sum(l1, red);
    if (tid == 0) {
        l0 += lb[0]; l1 += lb[1];
        float m = fmaxf(l0, l1);
        float e0 = expf(l0 - m), e1 = expf(l1 - m);
        float inv = 1.f / (e0 + e1);
        probs[2 * row + 0] = e0 * inv;
        probs[2 * row + 1] = e1 * inv;
        if (write_path) path[row] = (l1 > l0) ? 1.f : 0.f;
    }
}

// ---------------- launch -----------------------------------------------------
extern "C" void kernel_launch(void* const* d_in, const int* in_sizes, int n_in,
                              void* d_out, int out_size) {
    const float* ob  = (const float*)d_in[0];
    const int*   wi  = (const int*)d_in[1];
    const float* Wq  = (const float*)d_in[2];   const float* bq  = (const float*)d_in[3];
    const float* Wk  = (const float*)d_in[4];   const float* bk  = (const float*)d_in[5];
    const float* Wv  = (const float*)d_in[6];   const float* bv  = (const float*)d_in[7];
    const float* Wo  = (const float*)d_in[8];   const float* bo  = (const float*)d_in[9];
    const float* l1g = (const float*)d_in[10];  const float* l1b = (const float*)d_in[11];
    const float* W1f = (const float*)d_in[12];  const float* b1f = (const float*)d_in[13];
    const float* W2f = (const float*)d_in[14];  const float* b2f = (const float*)d_in[15];
    const float* l2g = (const float*)d_in[16];  const float* l2b = (const float*)d_in[17];
    const float* ng  = (const float*)d_in[18];  const float* nb  = (const float*)d_in[19];
    const float* lw  = (const float*)d_in[20];  const float* lb  = (const float*)d_in[21];

    float *feat, *qkv, *tmp, *tmp2, *x, *bqkv;
    __half *aexpA, *aexpB, *wqkvx, *wox, *w1x, *w2x;
    cudaGetSymbolAddress((void**)&feat, g_feat);
    cudaGetSymbolAddress((void**)&qkv,  g_qkv);
    cudaGetSymbolAddress((void**)&tmp,  g_tmp);
    cudaGetSymbolAddress((void**)&tmp2, g_tmp2);
    cudaGetSymbolAddress((void**)&x,    g_x);
    cudaGetSymbolAddress((void**)&bqkv, g_bqkv);
    cudaGetSymbolAddress((void**)&aexpA, g_aexpA);
    cudaGetSymbolAddress((void**)&aexpB, g_aexpB);
    cudaGetSymbolAddress((void**)&wqkvx, g_wqkv);
    cudaGetSymbolAddress((void**)&wox,  g_wo);
    cudaGetSymbolAddress((void**)&w1x,  g_w1);
    cudaGetSymbolAddress((void**)&w2x,  g_w2);

    cudaFuncSetAttribute(attn2_k, cudaFuncAttributeMaxDynamicSharedMemorySize, ATTN_SMEM);
    cudaFuncSetAttribute(gemm_f16_k, cudaFuncAttributeMaxDynamicSharedMemorySize, GEMM_SMEM);

    // 1: weight prep, 2: bias concat, 3: gather
    prep_weights_k<<<dim3(DFF/32, DFF/32, 6), 256>>>(Wq, Wk, Wv, Wo, W1f, W2f,
                                                     wqkvx, wox, w1x, w2x);
    concat_bias_k<<<3, 256>>>(bq, bk, bv, bqkv);
    gather_fused_k<<<BSZ, 256>>>(ob, wi, feat, aexpA);

    // 4: fused QKV GEMM (N=2304 -> 18 x-blocks of 128)
    gemm_f16_k<<<dim3(18, 128, 1), 512, GEMM_SMEM>>>(
        aexpA, wqkvx, bqkv, qkv, nullptr, nullptr, BW, NQKV, DD, DD, 0);

    // 5: attention (writes split ctx into aexpA)
    attn2_k<<<BSZ * HH, 512, ATTN_SMEM>>>(qkv, aexpA);

    // 6: Wo GEMM, split-K x2
    gemm_f16_k<<<dim3(6, 128, 2), 512, GEMM_SMEM>>>(
        aexpA, wox, bo, tmp, tmp2, nullptr, BW, DD, DD, DD/2, 0);

    // 7: LN1
    add_ln_k<<<BW, 256>>>(feat, tmp, tmp2, l1g, l1b, x, aexpA);

    // 8: FFN1 (relu + split epilogue -> aexpB)
    gemm_f16_k<<<dim3(24, 128, 1), 512, GEMM_SMEM>>>(
        aexpA, w1x, b1f, nullptr, nullptr, aexpB, BW, DFF, DD, DD, 1);

    // 9: FFN2, split-K x2
    gemm_f16_k<<<dim3(6, 128, 2), 512, GEMM_SMEM>>>(
        aexpB, w2x, b2f, tmp, tmp2, nullptr, BW, DD, DFF, DFF/2, 0);

    // 10: fused add + LN2 + LN3 + linear + softmax + argmax
    float* probs = (float*)d_out;
    float* path  = probs + (long)BW * 2;
    int wp = (out_size >= BW * 3) ? 1 : 0;
    final2_k<<<BW, 256>>>(x, tmp, tmp2, l2g, l2b, ng, nb, lw, lb, probs, path, wp);
}

// round 17
// speedup vs baseline: 1.6096x; 1.6096x over previous
#include <cuda_runtime.h>
#include <cuda_fp16.h>
#include <math.h>
#include <stdint.h>

#define BSZ 64
#define TT  512
#define DD  768
#define WW  255
#define HH  8
#define DHD 96
#define BW  (BSZ*WW)      // 16320
#define DFF 3072
#define NQKV 2304

// ---------------- scratch (device globals; no allocation allowed) ----------
static __device__ float  g_feat[BW*DD];
static __device__ float  g_qkv[(long)BW*NQKV];
static __device__ float  g_tmp[BW*DD];
static __device__ float  g_tmp2[BW*DD];
static __device__ float  g_x[BW*DD];
static __device__ __half g_aexpA[(long)BW*2*DD];     // [M, 1536] halfs
static __device__ __half g_aexpB[(long)BW*2*DFF];    // [M, 6144] halfs
static __device__ __half g_wqkv[NQKV*2*DD];          // [2304][1536]
static __device__ __half g_wo[DD*2*DD];
static __device__ __half g_w1[DFF*2*DD];             // [3072][1536]
static __device__ __half g_w2[DD*2*DFF];             // [768][6144]
static __device__ float  g_bqkv[NQKV];

// ---------------- helpers ----------------------------------------------------
#define CP16(d,s)  asm volatile("cp.async.cg.shared.global [%0], [%1], 16;" :: "r"(d), "l"(s))
#define CPCOMMIT() asm volatile("cp.async.commit_group;" ::: "memory")
#define CPWAIT0()  asm volatile("cp.async.wait_group 0;" ::: "memory")

#define LDSM4(r0,r1,r2,r3,addr) \
    asm volatile("ldmatrix.sync.aligned.m8n8.x4.shared.b16 {%0,%1,%2,%3}, [%4];" \
        : "=r"(r0), "=r"(r1), "=r"(r2), "=r"(r3) : "r"(addr))

__device__ __forceinline__ uint32_t smem_u32(const void* p){
    uint32_t a;
    asm("{ .reg .u64 t; cvta.to.shared.u64 t, %1; cvt.u32.u64 %0, t; }" : "=r"(a) : "l"(p));
    return a;
}

__device__ __forceinline__ void mma_f16(float* c, const uint32_t* a, const uint32_t* b){
    asm volatile(
        "mma.sync.aligned.m16n8k16.row.col.f32.f16.f16.f32 "
        "{%0,%1,%2,%3}, {%4,%5,%6,%7}, {%8,%9}, {%0,%1,%2,%3};"
        : "+f"(c[0]), "+f"(c[1]), "+f"(c[2]), "+f"(c[3])
        : "r"(a[0]), "r"(a[1]), "r"(a[2]), "r"(a[3]), "r"(b[0]), "r"(b[1]));
}

__device__ __forceinline__ void split2(float v, __half& h, __half& l){
    h = __float2half_rn(v);
    l = __float2half_rn(v - __half2float(h));
}

// ---- packed f32x2 (Blackwell FFMA2) ----
__device__ __forceinline__ unsigned long long pk2(float x, float y){
    unsigned long long r;
    asm("mov.b64 %0, {%1, %2};" : "=l"(r) : "f"(x), "f"(y));
    return r;
}
__device__ __forceinline__ void fma2(unsigned long long& acc, unsigned long long a,
                                     unsigned long long b){
    asm("fma.rn.f32x2 %0, %1, %2, %0;" : "+l"(acc) : "l"(a), "l"(b));
}
__device__ __forceinline__ float2 upk2(unsigned long long v){
    float x, y;
    asm("mov.b64 {%0, %1}, %2;" : "=f"(x), "=f"(y) : "l"(v));
    return make_float2(x, y);
}

// ---------------- fused weight prep: transpose + fp16 hi/lo split -----------
__global__ void prep_weights_k(
    const float* __restrict__ Wq, const float* __restrict__ Wk,
    const float* __restrict__ Wv, const float* __restrict__ Wo,
    const float* __restrict__ W1, const float* __restrict__ W2,
    __half* wqkv, __half* wo, __half* w1, __half* w2)
{
    __shared__ float t[32][33];
    int z = blockIdx.z;
    const float* W; __half* Bx; int K, N;
    switch (z) {
        case 0: W = Wq; Bx = wqkv;                 K = DD;  N = DD;  break;
        case 1: W = Wk; Bx = wqkv + 768L*2*DD;     K = DD;  N = DD;  break;
        case 2: W = Wv; Bx = wqkv + 1536L*2*DD;    K = DD;  N = DD;  break;
        case 3: W = Wo; Bx = wo;                   K = DD;  N = DD;  break;
        case 4: W = W1; Bx = w1;                   K = DD;  N = DFF; break;
        default:W = W2; Bx = w2;                   K = DFF; N = DD;  break;
    }
    int n0 = blockIdx.x * 32, k0 = blockIdx.y * 32;
    if (n0 >= N || k0 >= K) return;
    int tx = threadIdx.x & 31, ty = threadIdx.x >> 5;
    #pragma unroll
    for (int r = ty; r < 32; r += 8)
        t[r][tx] = W[(long)(k0 + r) * N + n0 + tx];
    __syncthreads();
    #pragma unroll
    for (int r = ty; r < 32; r += 8) {
        float v = t[tx][r];
        __half h, l; split2(v, h, l);
        long b = (long)(n0 + r) * (2 * K) + k0 + tx;
        Bx[b] = h;
        Bx[b + K] = l;
    }
}

__global__ void concat_bias_k(const float* __restrict__ bq, const float* __restrict__ bk,
                              const float* __restrict__ bv, float* __restrict__ bqkv) {
    int i = blockIdx.x * 256 + threadIdx.x;
    if (i < DD) {
        bqkv[i] = bq[i];
        bqkv[DD + i] = bk[i];
        bqkv[2*DD + i] = bv[i];
    }
}

// ---------------- fused gather: first-subtoken + copy + split ---------------
__global__ __launch_bounds__(256)
void gather_fused_k(const float* __restrict__ ob, const int* __restrict__ wi,
                    float* __restrict__ feat, __half* __restrict__ aexpA) {
    __shared__ int first[WW];
    int b = blockIdx.x, tid = threadIdx.x;
    for (int i = tid; i < WW; i += 256) first[i] = TT;
    __syncthreads();
    for (int t = tid; t < TT; t += 256) {
        int w = wi[b * TT + t];
        if (w >= 0 && w < WW) atomicMin(&first[w], t);
    }
    __syncthreads();
    for (int idx = tid; idx < WW * 192; idx += 256) {
        int row = idx / 192, c4 = idx % 192;
        int t = first[row]; if (t >= TT) t = 0;
        float4 val = ((const float4*)(ob + ((long)(b * TT + t)) * DD))[c4];
        long gr = (long)b * WW + row;
        ((float4*)(feat + gr * DD))[c4] = val;
        float vv[4] = {val.x, val.y, val.z, val.w};
        __half hs[4], ls[4];
        #pragma unroll
        for (int j = 0; j < 4; j++) split2(vv[j], hs[j], ls[j]);
        __half2* ph = (__half2*)(aexpA + gr * 1536 + c4 * 4);
        ph[0] = __halves2half2(hs[0], hs[1]);
        ph[1] = __halves2half2(hs[2], hs[3]);
        __half2* pl = (__half2*)(aexpA + gr * 1536 + 768 + c4 * 4);
        pl[0] = __halves2half2(ls[0], ls[1]);
        pl[1] = __halves2half2(ls[2], ls[3]);
    }
}

// ---------------- fp16x3 GEMM, 512 thr, KT=64 2-stage, ONE sync/iter --------
#define KT 64
#define SH 72
#define A_HALFS (128*SH)
#define B_HALFS (256*SH)
#define STG_HALFS (2*A_HALFS + 2*B_HALFS)
#define STG_BYTES (STG_HALFS*2)          // 110592
#define GEMM_SMEM (2*STG_BYTES)          // 221184

__global__ __launch_bounds__(512)
void gemm_f16_k(const __half* __restrict__ A2, const __half* __restrict__ B2,
                const float* __restrict__ bias, float* __restrict__ C0,
                float* __restrict__ C1, __half* __restrict__ Csplit,
                int M, int N, int Kfull, int Keff, int relu)
{
    extern __shared__ __half smh[];
    uint32_t sb = smem_u32(smh);
    int tid = threadIdx.x, wid = tid >> 5, lane = tid & 31;
    int g = lane >> 2, tg = lane & 3;
    int wm = wid & 1, wn = wid >> 1;            // 2 x 8 warps, warp tile 64x32
    int z = blockIdx.z;
    int kbase = z * Keff;
    float* C = z ? C1 : C0;
    const float* bp = z ? nullptr : bias;
    const int K2 = 2 * Kfull;
    const int S = Keff / KT;
    const long mrow0 = (long)blockIdx.y * 128;
    const long nrow0 = (long)blockIdx.x * 256;

    uint32_t aOff[4], bOff[2];
    {
        int r = wm * 64 + (lane & 15);
        int kc = (lane >> 4) * 8;
        #pragma unroll
        for (int mf = 0; mf < 4; mf++)
            aOff[mf] = (uint32_t)((r + mf * 16) * (SH * 2) + kc * 2);
        int q = lane >> 3, rl = lane & 7;
        int nn = wn * 32 + ((q >> 1) * 8) + rl;
        int kk = (q & 1) * 8;
        #pragma unroll
        for (int p = 0; p < 2; p++)
            bOff[p] = (uint32_t)((nn + p * 16) * (SH * 2) + kk * 2);
    }

    float acc[4][4][4];
    #pragma unroll
    for (int i = 0; i < 4; i++)
        #pragma unroll
        for (int j = 0; j < 4; j++)
            #pragma unroll
            for (int r = 0; r < 4; r++) acc[i][j][r] = 0.f;

    #define LOAD_STAGE(ks, slot) do { \
        uint32_t base_ = sb + (slot) * STG_BYTES; \
        _Pragma("unroll") \
        for (int i_ = 0; i_ < 2; i_++) { \
            int c_ = i_ * 512 + tid; int r_ = c_ >> 3, q_ = c_ & 7; \
            long grow_ = mrow0 + r_; if (grow_ >= M) grow_ = M - 1; \
            const __half* s_ = A2 + grow_ * K2 + kbase + (ks) * KT + q_ * 8; \
            uint32_t d_ = base_ + (uint32_t)(r_ * (SH*2) + q_ * 16); \
            CP16(d_, s_); \
            CP16(d_ + A_HALFS*2, s_ + Kfull); \
        } \
        _Pragma("unroll") \
        for (int i_ = 0; i_ < 4; i_++) { \
            int c_ = i_ * 512 + tid; int r_ = c_ >> 3, q_ = c_ & 7; \
            const __half* s_ = B2 + (long)(nrow0 + r_) * K2 + kbase + (ks) * KT + q_ * 8; \
            uint32_t d_ = base_ + (uint32_t)(2*A_HALFS*2 + r_ * (SH*2) + q_ * 16); \
            CP16(d_, s_); \
            CP16(d_ + B_HALFS*2, s_ + Kfull); \
        } \
    } while (0)

    LOAD_STAGE(0, 0); CPCOMMIT();

    for (int it = 0; it < S; it++) {
        int slot = it & 1;
        CPWAIT0();
        __syncthreads();
        if (it + 1 < S) { LOAD_STAGE(it + 1, (it + 1) & 1); CPCOMMIT(); }

        uint32_t stAh = sb + slot * STG_BYTES;
        uint32_t stAl = stAh + A_HALFS * 2;
        uint32_t stBh = stAh + 2 * A_HALFS * 2;
        uint32_t stBl = stBh + B_HALFS * 2;

        #pragma unroll
        for (int ks = 0; ks < 4; ks++) {
            uint32_t kb = (uint32_t)(ks * 32);
            uint32_t ah[4][4], al[4][4], bh[2][4], bl[2][4];
            #pragma unroll
            for (int mf = 0; mf < 4; mf++)
                LDSM4(ah[mf][0], ah[mf][1], ah[mf][2], ah[mf][3], stAh + aOff[mf] + kb);
            #pragma unroll
            for (int mf = 0; mf < 4; mf++)
                LDSM4(al[mf][0], al[mf][1], al[mf][2], al[mf][3], stAl + aOff[mf] + kb);
            #pragma unroll
            for (int p = 0; p < 2; p++)
                LDSM4(bh[p][0], bh[p][1], bh[p][2], bh[p][3], stBh + bOff[p] + kb);
            #pragma unroll
            for (int p = 0; p < 2; p++)
                LDSM4(bl[p][0], bl[p][1], bl[p][2], bl[p][3], stBl + bOff[p] + kb);

            #pragma unroll
            for (int mf = 0; mf < 4; mf++)
                #pragma unroll
                for (int p = 0; p < 2; p++) {
                    mma_f16(acc[mf][2*p],   ah[mf], &bh[p][0]);
                    mma_f16(acc[mf][2*p+1], ah[mf], &bh[p][2]);
                }
            #pragma unroll
            for (int mf = 0; mf < 4; mf++)
                #pragma unroll
                for (int p = 0; p < 2; p++) {
                    mma_f16(acc[mf][2*p],   ah[mf], &bl[p][0]);
                    mma_f16(acc[mf][2*p+1], ah[mf], &bl[p][2]);
                }
            #pragma unroll
            for (int mf = 0; mf < 4; mf++)
                #pragma unroll
                for (int p = 0; p < 2; p++) {
                    mma_f16(acc[mf][2*p],   al[mf], &bh[p][0]);
                    mma_f16(acc[mf][2*p+1], al[mf], &bh[p][2]);
                }
        }
    }

    // epilogue
    #pragma unroll
    for (int mf = 0; mf < 4; mf++) {
        long r0 = mrow0 + wm * 64 + mf * 16 + g;
        long r1 = r0 + 8;
        #pragma unroll
        for (int nf = 0; nf < 4; nf++) {
            long col = nrow0 + wn * 32 + nf * 8 + 2 * tg;
            float b0 = bp ? bp[col] : 0.f, b1 = bp ? bp[col + 1] : 0.f;
            float v0 = acc[mf][nf][0] + b0, v1 = acc[mf][nf][1] + b1;
            float v2 = acc[mf][nf][2] + b0, v3 = acc[mf][nf][3] + b1;
            if (relu) {
                v0 = fmaxf(v0, 0.f); v1 = fmaxf(v1, 0.f);
                v2 = fmaxf(v2, 0.f); v3 = fmaxf(v3, 0.f);
            }
            if (Csplit) {
                __half h0, l0, h1, l1;
                if (r0 < M) {
                    split2(v0, h0, l0); split2(v1, h1, l1);
                    *(__half2*)&Csplit[r0 * (2*(long)N) + col]     = __halves2half2(h0, h1);
                    *(__half2*)&Csplit[r0 * (2*(long)N) + N + col] = __halves2half2(l0, l1);
                }
                if (r1 < M) {
                    split2(v2, h0, l0); split2(v3, h1, l1);
                    *(__half2*)&Csplit[r1 * (2*(long)N) + col]     = __halves2half2(h0, h1);
                    *(__half2*)&Csplit[r1 * (2*(long)N) + N + col] = __halves2half2(l0, l1);
                }
            } else {
                if (r0 < M) *(float2*)&C[r0 * N + col] = make_float2(v0, v1);
                if (r1 < M) *(float2*)&C[r1 * N + col] = make_float2(v2, v3);
            }
        }
    }
}

// ---------------- attention: 512 thr, pair-interleaved K, packed f32x2 ------
#define AT_KS   (96*WW)          // 24480 floats (even)
#define AT_VS   (WW*97 + 1)      // 24736 floats (even -> ps 8B-aligned)
#define AT_PS   (32*256)
#define ATTN_SMEM ((AT_KS + AT_VS + AT_PS) * 4)   // 229,632 B

__global__ __launch_bounds__(512)
void attn2_k(const float* __restrict__ qkv, __half* __restrict__ ctx_split) {
    int b = blockIdx.x / HH, h = blockIdx.x % HH;
    extern __shared__ float smfa[];
    float* ks_t = smfa;                // pair-interleaved [48][255][2]
    float* vs   = ks_t + AT_KS;
    float* ps   = vs + AT_VS;          // even float offset -> 8B aligned
    float* qs   = ps;
    int tid = threadIdx.x, warp = tid >> 5, lane = tid & 31;

    for (int idx = tid; idx < WW * DHD; idx += 512) {
        int key = idx / DHD, d = idx % DHD;
        long gg = ((long)(b * WW + key)) * NQKV + h * DHD + d;
        ks_t[(d >> 1) * (2 * WW) + key * 2 + (d & 1)] = qkv[gg + DD];
        vs[key * 97 + d] = qkv[gg + 2 * DD];
    }
    __syncthreads();

    const float scale = 0.10206207261596575f;
    int d0 = lane * 3;

    for (int row0 = 0; row0 < 256; row0 += 32) {
        for (int idx = tid; idx < 32 * DHD; idx += 512) {
            int r = idx / DHD, d = idx % DHD;
            int row = row0 + r;
            qs[r * DHD + d] = (row < WW)
                ? qkv[((long)(b * WW + row)) * NQKV + h * DHD + d] : 0.f;
        }
        __syncthreads();

        unsigned long long acc2[8][2];
        #pragma unroll
        for (int kk = 0; kk < 8; kk++) {
            acc2[kk][0] = 0ull; acc2[kk][1] = 0ull;
        }

        const float* qr = &qs[(warp * 2) * DHD];
        #pragma unroll 4
        for (int dp = 0; dp < 48; dp++) {
            float2 t0 = *(const float2*)&qr[2 * dp];
            float2 t1 = *(const float2*)&qr[DHD + 2 * dp];
            unsigned long long qp0 = pk2(t0.x, t0.y);
            unsigned long long qp1 = pk2(t1.x, t1.y);
            const float2* kd = (const float2*)&ks_t[dp * (2 * WW)];
            #pragma unroll
            for (int kk = 0; kk < 8; kk++) {
                int key = lane + kk * 32;
                float2 kv2 = kd[key];
                unsigned long long kvp = pk2(kv2.x, kv2.y);
                fma2(acc2[kk][0], kvp, qp0);
                fma2(acc2[kk][1], kvp, qp1);
            }
        }
        float sc[8][2];
        #pragma unroll
        for (int kk = 0; kk < 8; kk++)
            #pragma unroll
            for (int r = 0; r < 2; r++) {
                float2 t = upk2(acc2[kk][r]);
                sc[kk][r] = t.x + t.y;
            }
        __syncthreads();

        float inv[2], mx[2];
        #pragma unroll
        for (int r = 0; r < 2; r++) {
            float m = -1e30f;
            #pragma unroll
            for (int kk = 0; kk < 8; kk++) {
                int key = lane + kk * 32;
                float s = (key < WW) ? sc[kk][r] * scale : -1e30f;
                sc[kk][r] = s;
                m = fmaxf(m, s);
            }
            #pragma unroll
            for (int o = 16; o; o >>= 1) m = fmaxf(m, __shfl_xor_sync(0xffffffffu, m, o));
            mx[r] = m;
        }
        #pragma unroll
        for (int r = 0; r < 2; r++) {
            float sum = 0.f;
            #pragma unroll
            for (int kk = 0; kk < 8; kk++) {
                float e = (sc[kk][r] > -1e29f) ? __expf(sc[kk][r] - mx[r]) : 0.f;
                sc[kk][r] = e;
                sum += e;
            }
            #pragma unroll
            for (int o = 16; o; o >>= 1) sum += __shfl_xor_sync(0xffffffffu, sum, o);
            inv[r] = 1.f / sum;
        }
        #pragma unroll
        for (int r = 0; r < 2; r++)
            #pragma unroll
            for (int kk = 0; kk < 8; kk++)
                ps[(warp * 2 + r) * 256 + lane + kk * 32] = sc[kk][r] * inv[r];
        __syncwarp();

        unsigned long long ap[2][3];
        #pragma unroll
        for (int r = 0; r < 2; r++)
            #pragma unroll
            for (int j = 0; j < 3; j++) ap[r][j] = 0ull;

        const float* pr = &ps[(warp * 2) * 256];
        #pragma unroll 2
        for (int key = 0; key < WW - 1; key += 2) {
            const float* vr0 = &vs[key * 97 + d0];
            const float* vr1 = vr0 + 97;
            unsigned long long vvp0 = pk2(vr0[0], vr1[0]);
            unsigned long long vvp1 = pk2(vr0[1], vr1[1]);
            unsigned long long vvp2 = pk2(vr0[2], vr1[2]);
            #pragma unroll
            for (int r = 0; r < 2; r++) {
                float2 pp = *(const float2*)&pr[r * 256 + key];
                unsigned long long ppk = pk2(pp.x, pp.y);
                fma2(ap[r][0], ppk, vvp0);
                fma2(ap[r][1], ppk, vvp1);
                fma2(ap[r][2], ppk, vvp2);
            }
        }
        const float* vrt = &vs[(WW - 1) * 97 + d0];
        #pragma unroll
        for (int r = 0; r < 2; r++) {
            int row = row0 + warp * 2 + r;
            if (row < WW) {
                float pt = pr[r * 256 + (WW - 1)];
                long base = ((long)(b * WW + row)) * 1536 + h * DHD + d0;
                #pragma unroll
                for (int j = 0; j < 3; j++) {
                    float2 t = upk2(ap[r][j]);
                    float val = t.x + t.y + pt * vrt[j];
                    __half hh, ll; split2(val, hh, ll);
                    ctx_split[base + j] = hh;
                    ctx_split[base + 768 + j] = ll;
                }
            }
        }
        __syncthreads();
    }
}

// ---------------- block reduce helper ---------------------------------------
__device__ __forceinline__ float block_reduce_sum(float val, float* red) {
    int lane = threadIdx.x & 31, warp = threadIdx.x >> 5;
    #pragma unroll
    for (int o = 16; o; o >>= 1) val += __shfl_xor_sync(0xffffffffu, val, o);
    if (lane == 0) red[warp] = val;
    __syncthreads();
    if (warp == 0) {
        float v = (lane < 8) ? red[lane] : 0.f;
        #pragma unroll
        for (int o = 4; o; o >>= 1) v += __shfl_xor_sync(0xffffffffu, v, o);
        if (lane == 0) red[0] = v;
    }
    __syncthreads();
    float r = red[0];
    __syncthreads();
    return r;
}

// ---------------- residual add (2 partials) + layernorm + split out ---------
__global__ __launch_bounds__(256)
void add_ln_k(const float* __restrict__ X, const float* __restrict__ Y1,
              const float* __restrict__ Y2,
              const float* __restrict__ g, const float* __restrict__ bb,
              float* __restrict__ out, __half* __restrict__ split) {
    __shared__ float red[32];
    int row = blockIdx.x, tid = threadIdx.x;
    const float* x = X + (long)row * DD;
    const float* y1 = Y1 + (long)row * DD;
    const float* y2 = Y2 + (long)row * DD;
    float v[3];
    float s = 0.f;
    #pragma unroll
    for (int i = 0; i < 3; i++) {
        int c = tid + 256 * i;
        v[i] = x[c] + y1[c] + y2[c];
        s += v[i];
    }
    float mean = block_reduce_sum(s, red) * (1.f / DD);
    float vs = 0.f;
    #pragma unroll
    for (int i = 0; i < 3; i++) { float d = v[i] - mean; vs += d * d; }
    float var = block_reduce_sum(vs, red) * (1.f / DD);
    float rstd = rsqrtf(var + 1e-5f);
    float* o = out + (long)row * DD;
    #pragma unroll
    for (int i = 0; i < 3; i++) {
        int c = tid + 256 * i;
        float val = (v[i] - mean) * rstd * g[c] + bb[c];
        o[c] = val;
        if (split) {
            __half h, l; split2(val, h, l);
            split[(long)row * 1536 + c] = h;
            split[(long)row * 1536 + 768 + c] = l;
        }
    }
}

// ---------------- final: add + LN2 + LN3 + linear(2) + softmax + argmax -----
__global__ __launch_bounds__(256)
void final2_k(const float* __restrict__ X, const float* __restrict__ Y1,
              const float* __restrict__ Y2,
              const float* __restrict__ g2, const float* __restrict__ b2,
              const float* __restrict__ g3, const float* __restrict__ b3,
              const float* __restrict__ lw, const float* __restrict__ lb,
              float* __restrict__ probs, float* __restrict__ path, int write_path) {
    __shared__ float red[32];
    int row = blockIdx.x, tid = threadIdx.x;
    const float* x = X + (long)row * DD;
    const float* y1 = Y1 + (long)row * DD;
    const float* y2 = Y2 + (long)row * DD;
    float v[3];
    float s = 0.f;
    #pragma unroll
    for (int i = 0; i < 3; i++) {
        int c = tid + 256 * i;
        v[i] = x[c] + y1[c] + y2[c];
        s += v[i];
    }
    float mean = block_reduce_sum(s, red) * (1.f / DD);
    float vs = 0.f;
    #pragma unroll
    for (int i = 0; i < 3; i++) { float d = v[i] - mean; vs += d * d; }
    float var = block_reduce_sum(vs, red) * (1.f / DD);
    float rstd = rsqrtf(var + 1e-5f);
    #pragma unroll
    for (int i = 0; i < 3; i++) {
        int c = tid + 256 * i;
        v[i] = (v[i] - mean) * rstd * g2[c] + b2[c];
    }
    s = 0.f;
    #pragma unroll
    for (int i = 0; i < 3; i++) s += v[i];
    mean = block_reduce_sum(s, red) * (1.f / DD);
    vs = 0.f;
    #pragma unroll
    for (int i = 0; i < 3; i++) { float d = v[i] - mean; vs += d * d; }
    var = block_reduce_sum(vs, red) * (1.f / DD);
    rstd = rsqrtf(var + 1e-5f);
    float l0 = 0.f, l1 = 0.f;
    #pragma unroll
    for (int i = 0; i < 3; i++) {
        int c = tid + 256 * i;
        float yv = (v[i] - mean) * rstd * g3[c] + b3[c];
        l0 += yv * lw[2 * c + 0];
        l1 += yv * lw[2 * c + 1];
    }
    l0 = block_reduce_sum(l0, red);
    l1 = block_reduce_sum(l1, red);
    if (tid == 0) {
        l0 += lb[0]; l1 += lb[1];
        float m = fmaxf(l0, l1);
        float e0 = expf(l0 - m), e1 = expf(l1 - m);
        float inv = 1.f / (e0 + e1);
        probs[2 * row + 0] = e0 * inv;
        probs[2 * row + 1] = e1 * inv;
        if (write_path) path[row] = (l1 > l0) ? 1.f : 0.f;
    }
}

// ---------------- launch -----------------------------------------------------
extern "C" void kernel_launch(void* const* d_in, const int* in_sizes, int n_in,
                              void* d_out, int out_size) {
    const float* ob  = (const float*)d_in[0];
    const int*   wi  = (const int*)d_in[1];
    const float* Wq  = (const float*)d_in[2];   const float* bq  = (const float*)d_in[3];
    const float* Wk  = (const float*)d_in[4];   const float* bk  = (const float*)d_in[5];
    const float* Wv  = (const float*)d_in[6];   const float* bv  = (const float*)d_in[7];
    const float* Wo  = (const float*)d_in[8];   const float* bo  = (const float*)d_in[9];
    const float* l1g = (const float*)d_in[10];  const float* l1b = (const float*)d_in[11];
    const float* W1f = (const float*)d_in[12];  const float* b1f = (const float*)d_in[13];
    const float* W2f = (const float*)d_in[14];  const float* b2f = (const float*)d_in[15];
    const float* l2g = (const float*)d_in[16];  const float* l2b = (const float*)d_in[17];
    const float* ng  = (const float*)d_in[18];  const float* nb  = (const float*)d_in[19];
    const float* lw  = (const float*)d_in[20];  const float* lb  = (const float*)d_in[21];

    float *feat, *qkv, *tmp, *tmp2, *x, *bqkv;
    __half *aexpA, *aexpB, *wqkvx, *wox, *w1x, *w2x;
    cudaGetSymbolAddress((void**)&feat, g_feat);
    cudaGetSymbolAddress((void**)&qkv,  g_qkv);
    cudaGetSymbolAddress((void**)&tmp,  g_tmp);
    cudaGetSymbolAddress((void**)&tmp2, g_tmp2);
    cudaGetSymbolAddress((void**)&x,    g_x);
    cudaGetSymbolAddress((void**)&bqkv, g_bqkv);
    cudaGetSymbolAddress((void**)&aexpA, g_aexpA);
    cudaGetSymbolAddress((void**)&aexpB, g_aexpB);
    cudaGetSymbolAddress((void**)&wqkvx, g_wqkv);
    cudaGetSymbolAddress((void**)&wox,  g_wo);
    cudaGetSymbolAddress((void**)&w1x,  g_w1);
    cudaGetSymbolAddress((void**)&w2x,  g_w2);

    cudaFuncSetAttribute(attn2_k, cudaFuncAttributeMaxDynamicSharedMemorySize, ATTN_SMEM);
    cudaFuncSetAttribute(gemm_f16_k, cudaFuncAttributeMaxDynamicSharedMemorySize, GEMM_SMEM);

    // 1: weight prep, 2: bias concat, 3: gather
    prep_weights_k<<<dim3(DFF/32, DFF/32, 6), 256>>>(Wq, Wk, Wv, Wo, W1f, W2f,
                                                     wqkvx, wox, w1x, w2x);
    concat_bias_k<<<3, 256>>>(bq, bk, bv, bqkv);
    gather_fused_k<<<BSZ, 256>>>(ob, wi, feat, aexpA);

    // 4: fused QKV GEMM
    gemm_f16_k<<<dim3(9, 128, 1), 512, GEMM_SMEM>>>(
        aexpA, wqkvx, bqkv, qkv, nullptr, nullptr, BW, NQKV, DD, DD, 0);

    // 5: attention (writes split ctx into aexpA)
    attn2_k<<<BSZ * HH, 512, ATTN_SMEM>>>(qkv, aexpA);

    // 6: Wo GEMM, split-K x2
    gemm_f16_k<<<dim3(3, 128, 2), 512, GEMM_SMEM>>>(
        aexpA, wox, bo, tmp, tmp2, nullptr, BW, DD, DD, DD/2, 0);

    // 7: LN1
    add_ln_k<<<BW, 256>>>(feat, tmp, tmp2, l1g, l1b, x, aexpA);

    // 8: FFN1 (relu + split epilogue -> aexpB)
    gemm_f16_k<<<dim3(12, 128, 1), 512, GEMM_SMEM>>>(
        aexpA, w1x, b1f, nullptr, nullptr, aexpB, BW, DFF, DD, DD, 1);

    // 9: FFN2, split-K x2
    gemm_f16_k<<<dim3(3, 128, 2), 512, GEMM_SMEM>>>(
        aexpB, w2x, b2f, tmp, tmp2, nullptr, BW, DD, DFF, DFF/2, 0);

    // 10: fused add + LN2 + LN3 + linear + softmax + argmax
    float* probs = (float*)d_out;
    float* path  = probs + (long)BW * 2;
    int wp = (out_size >= BW * 3) ? 1 : 0;
    final2_k<<<BW, 256>>>(x, tmp, tmp2, l2g, l2b, ng, nb, lw, lb, probs, path, wp);
}